// round 5
// baseline (speedup 1.0000x reference)
#include <cuda_runtime.h>
#include <math.h>

// Problem constants (fixed by setup_inputs)
#define B 4
#define H 320
#define W 320
#define NPIX   (B * H * W)
#define TILE   2                      // rows per block
#define HALO   8                      // staged halo above/below
#define NSTAGE (TILE + 2 * HALO)      // 18 staged rows -> 18-bit column mask
#define NBLOCKS (B * (H / TILE))      // 640
#define LAMBDA 1.0f

__device__ double g_acc;
__device__ unsigned int g_count;

// ---------------------------------------------------------------------------
// One block per 2-row strip; 320 threads (one per column); grid = 640 so
// 4+ blocks are resident per SM (occupancy was the round-4 limiter).
//  1. Each thread folds 18 staged target rows into an 18-bit seed mask
//     (independent coalesced LDG, pure-ALU vertical resolve via clz/ffs,
//     window >= +-8; fallback P ~ 7.6e-6 per pixel).
//  2. g2 rows -> smem, ONE barrier, pruned horizontal search with r=1..2
//     peeled unconditionally (common case), loss in a register.
//  3. Block reduce + one atomicAdd; last block finalizes mean + resets
//     globals (graph-replay safe).
// ---------------------------------------------------------------------------
__global__ void __launch_bounds__(W)
edt_tile_loss_kernel(const float* __restrict__ logits,
                     const int*   __restrict__ targets,
                     float*       __restrict__ out)
{
    __shared__ float s_g2[TILE][W];
    __shared__ float warp_sums[W / 32];

    const int tile = blockIdx.x;                   // 0 .. NBLOCKS-1
    const int b    = tile / (H / TILE);
    const int h0   = (tile % (H / TILE)) * TILE;   // first row of strip
    const int wo   = threadIdx.x;                  // column
    const size_t img_base = (size_t)b * H * W;

    const int*   tcol = targets + img_base + wo;
    const float* lcol = logits  + img_base + wo;

    // --- logits for my pixels (independent, issue early) ---
    float xv[TILE];
    #pragma unroll
    for (int j = 0; j < TILE; ++j)
        xv[j] = lcol[(h0 + j) * W];

    // --- build 18-bit column seed mask (rows h0-HALO .. h0+TILE+HALO-1) ---
    unsigned int mask = 0u;
    #pragma unroll
    for (int r = 0; r < NSTAGE; ++r) {
        const int hh = h0 - HALO + r;
        int v = 0;
        if (hh >= 0 && hh < H) v = tcol[hh * W];
        mask |= (unsigned int)(v != 0) << r;
    }

    // --- vertical resolve per pixel (pure ALU) ---
    #pragma unroll
    for (int j = 0; j < TILE; ++j) {
        const int c = j + HALO;                                    // staged idx
        const unsigned int below = mask & ((1u << (c + 1)) - 1u);  // bits <= c
        const unsigned int above = mask >> c;                      // bits >= c
        int d_up = 1 << 20, d_dn = 1 << 20;
        if (below) d_up = c - (31 - __clz(below));
        if (above) d_dn = __ffs(above) - 1;
        const int v = min(d_up, d_dn);
        float g2;
        if (mask != 0u) {
            g2 = (float)(v * v);
        } else {
            // Fallback: no seed in staged window (P ~ 7.6e-6).
            const int h = h0 + j;
            g2 = INFINITY;
            for (int r = HALO + 1; r < H; ++r) {
                const int hu = h - r, hd = h + r;
                bool found = false;
                if (hu >= 0 && tcol[hu * W] != 0) found = true;
                if (hd < H  && tcol[hd * W] != 0) found = true;
                if (found) { g2 = (float)(r * r); break; }
            }
        }
        s_g2[j][wo] = g2;
    }
    __syncthreads();

    // --- horizontal pruned search + fused loss ---
    float acc = 0.0f;
    #pragma unroll
    for (int j = 0; j < TILE; ++j) {
        const float* s = s_g2[j];
        float best = s[wo];
        // Peel r=1,2 unconditionally (covers the vast majority of pixels)
        {
            const int l1 = wo - 1, r1 = wo + 1;
            if (l1 >= 0) best = fminf(best, s[l1] + 1.0f);
            if (r1 < W)  best = fminf(best, s[r1] + 1.0f);
            const int l2 = wo - 2, r2 = wo + 2;
            if (4.0f < best) {
                if (l2 >= 0) best = fminf(best, s[l2] + 4.0f);
                if (r2 < W)  best = fminf(best, s[r2] + 4.0f);
            }
        }
        for (int r = 3; r < W; ++r) {
            const float rr = (float)(r * r);
            if (rr >= best) break;
            const int lo = wo - r;
            const int hi = wo + r;
            if (lo >= 0) best = fminf(best, s[lo] + rr);
            if (hi < W)  best = fminf(best, s[hi] + rr);
        }
        const float d = sqrtf(best);
        const float p = 1.0f / (1.0f + __expf(-xv[j]));
        acc += p * d + LAMBDA * (1.0f - p);
    }

    // --- block reduce + global accumulate ---
    #pragma unroll
    for (int off = 16; off > 0; off >>= 1)
        acc += __shfl_down_sync(0xFFFFFFFFu, acc, off);

    const int lane = wo & 31;
    const int wid  = wo >> 5;
    if (lane == 0) warp_sums[wid] = acc;
    __syncthreads();

    if (wid == 0 && lane == 0) {
        float v = 0.0f;
        #pragma unroll
        for (int i = 0; i < W / 32; ++i) v += warp_sums[i];
        atomicAdd(&g_acc, (double)v);
        __threadfence();
        const unsigned int done = atomicAdd(&g_count, 1u);
        if (done == NBLOCKS - 1) {
            out[0] = (float)(g_acc / (double)NPIX);
            g_acc = 0.0;
            g_count = 0u;
        }
    }
}

extern "C" void kernel_launch(void* const* d_in, const int* in_sizes, int n_in,
                              void* d_out, int out_size)
{
    const float* logits  = (const float*)d_in[0];
    const int*   targets = (const int*)d_in[1];
    float*       out     = (float*)d_out;

    (void)in_sizes; (void)n_in; (void)out_size;

    edt_tile_loss_kernel<<<NBLOCKS, W>>>(logits, targets, out);
}